// round 13
// baseline (speedup 1.0000x reference)
#include <cuda_runtime.h>

// Fixed problem shape
constexpr int B_  = 32;
constexpr int C_  = 256;
constexpr int N_  = 4608;         // 96*48
constexpr int N4  = N_ / 4;       // 1152
constexpr int N2  = N_ / 2;       // 2304

// Batch split
constexpr int SPLITS = 2;
constexpr int BH     = B_ / SPLITS;   // 16

// k1: float2 per thread, C split into 8 groups of 32 channels
constexpr int K1T       = 128;
constexpr int CH        = 8;
constexpr int CHC       = C_ / CH;    // 32
constexpr int NTM       = N2 / K1T;   // 18 tiles
constexpr int K1_UNROLL = 16;

// k3: 384 threads, 2 channels per block, ALL loads issued up-front
constexpr int K3T  = 384;
constexpr int K3R  = 2;
constexpr int K3IT = N4 / K3T;        // 3

// Scratch (__device__ globals: allocation-free rule)
__device__ float2   g_G[CH][B_ * N2];
__device__ float2   g_P[CH][B_ * N2];
__device__ float2   g_T[CH][B_ * N2];
__device__ float    g_theta[B_ * N_];
__device__ float    g_sp[B_ * NTM];
__device__ unsigned g_cnt[B_ * NTM];   // zero-init; self-resetting

// ---------------------------------------------------------------------------
// Kernel 1: partial dots over a 32-channel group (float2 per thread).
// Last-arriving block of each (b,tile) merges the CH partials (fixed-order
// math on identical data => deterministic).
// ---------------------------------------------------------------------------
__global__ __launch_bounds__(K1T)
void k1_dots(const float* __restrict__ x,
             const float* __restrict__ gw, const float* __restrict__ gb,
             const float* __restrict__ tw, const float* __restrict__ tb,
             const float* __restrict__ pw, const float* __restrict__ pb,
             int bbase)
{
    __shared__ float swt[3 * CHC];
    const int tid  = threadIdx.x;
    const int tile = blockIdx.x;
    const int ch   = blockIdx.y;
    const int b    = bbase + blockIdx.z;

    if (tid < CHC) {
        swt[tid]           = gw[ch * CHC + tid];
        swt[CHC + tid]     = tw[ch * CHC + tid];
        swt[2 * CHC + tid] = pw[ch * CHC + tid];
    }
    __syncthreads();

    const int n2 = tile * K1T + tid;
    const float2* xr = reinterpret_cast<const float2*>(x)
                       + ((size_t)b * C_ + (size_t)ch * CHC) * N2 + n2;

    float2 ga = make_float2(0.f, 0.f);
    float2 ta = make_float2(0.f, 0.f);
    float2 pa = make_float2(0.f, 0.f);

    #pragma unroll
    for (int c0 = 0; c0 < CHC; c0 += K1_UNROLL) {
        float2 xv[K1_UNROLL];
        #pragma unroll
        for (int j = 0; j < K1_UNROLL; j++)
            xv[j] = __ldg(xr + (size_t)(c0 + j) * N2);
        #pragma unroll
        for (int j = 0; j < K1_UNROLL; j++) {
            const int c = c0 + j;
            const float w0 = swt[c];
            const float w1 = swt[CHC + c];
            const float w2 = swt[2 * CHC + c];
            ga.x = fmaf(w0, xv[j].x, ga.x); ga.y = fmaf(w0, xv[j].y, ga.y);
            ta.x = fmaf(w1, xv[j].x, ta.x); ta.y = fmaf(w1, xv[j].y, ta.y);
            pa.x = fmaf(w2, xv[j].x, pa.x); pa.y = fmaf(w2, xv[j].y, pa.y);
        }
    }

    const size_t o = (size_t)b * N2 + n2;
    g_G[ch][o] = ga;
    g_T[ch][o] = ta;
    g_P[ch][o] = pa;

    // -------- last-arriver merge --------
    __threadfence();
    __syncthreads();
    __shared__ int sLast;
    if (tid == 0) {
        const int idx = b * NTM + tile;
        const unsigned old = atomicAdd(&g_cnt[idx], 1u);
        const int last = (old == CH - 1);
        if (last) g_cnt[idx] = 0;          // self-reset for next launch
        sLast = last;
    }
    __syncthreads();
    if (!sLast) return;

    const float gb0 = __ldg(gb), tb0 = __ldg(tb), pb0 = __ldg(pb);

    float2 G = make_float2(gb0, gb0);
    float2 P = make_float2(pb0, pb0);
    float2 T = make_float2(tb0, tb0);
    #pragma unroll
    for (int h = 0; h < CH; h++) {         // fixed order
        const float2 gv = g_G[h][o]; G.x += gv.x; G.y += gv.y;
        const float2 pv = g_P[h][o]; P.x += pv.x; P.y += pv.y;
        const float2 tv = g_T[h][o]; T.x += tv.x; T.y += tv.y;
    }
    reinterpret_cast<float2*>(g_theta)[o] = T;

    float pg = G.x * P.x + G.y * P.y;
    #pragma unroll
    for (int off = 16; off > 0; off >>= 1)
        pg += __shfl_xor_sync(0xffffffffu, pg, off);

    __shared__ float red[K1T / 32];
    if ((tid & 31) == 0) red[tid >> 5] = pg;
    __syncthreads();
    if (tid == 0) {
        float s = 0.f;
        #pragma unroll
        for (int w = 0; w < K1T / 32; w++) s += red[w];
        g_sp[b * NTM + tile] = s;
    }
}

// ---------------------------------------------------------------------------
// Kernel 3: z = theta*ca + cd + x, 2 channels per block, 384 threads.
// ALL 9 float4 loads issued before any compute/store (covers DRAM latency).
// At the 6.7 TB/s DRAM roofline — unchanged from R12.
// ---------------------------------------------------------------------------
__global__ __launch_bounds__(K3T)
void k3_epilogue(const float* __restrict__ x, float* __restrict__ z,
                 const float* __restrict__ Ww, const float* __restrict__ Wb,
                 const float* __restrict__ gamma, const float* __restrict__ beta,
                 const float* __restrict__ mean,  const float* __restrict__ var,
                 int bbase)
{
    const int tid = threadIdx.x;
    const int cg  = blockIdx.x;               // 0..127
    const int b   = bbase + blockIdx.y;

    float s = 0.f;
    #pragma unroll
    for (int t = 0; t < NTM; t++) s += g_sp[b * NTM + t];   // fixed order
    s *= (1.f / (float)N_);

    const int c0 = cg * K3R;
    const float inv0 = __ldg(gamma + c0)     * rsqrtf(__ldg(var + c0)     + 1e-5f);
    const float inv1 = __ldg(gamma + c0 + 1) * rsqrtf(__ldg(var + c0 + 1) + 1e-5f);
    const float ca0 = s * __ldg(Ww + c0)     * inv0;
    const float ca1 = s * __ldg(Ww + c0 + 1) * inv1;
    const float cd0 = (__ldg(Wb + c0)     - __ldg(mean + c0))     * inv0 + __ldg(beta + c0);
    const float cd1 = (__ldg(Wb + c0 + 1) - __ldg(mean + c0 + 1)) * inv1 + __ldg(beta + c0 + 1);

    const size_t row0 = ((size_t)b * C_ + c0) * N4;
    const float4* xr0 = reinterpret_cast<const float4*>(x) + row0;
    const float4* xr1 = xr0 + N4;
    float4*       zr0 = reinterpret_cast<float4*>(z) + row0;
    float4*       zr1 = zr0 + N4;
    const float4* th  = reinterpret_cast<const float4*>(g_theta) + (size_t)b * N4;

    // ---- issue ALL loads first (9 float4 in flight per thread) ----
    float4 tv[K3IT], av[K3IT], bv[K3IT];
    #pragma unroll
    for (int k = 0; k < K3IT; k++) {
        const int i = k * K3T + tid;
        tv[k] = __ldg(th + i);
        av[k] = __ldcs(xr0 + i);
        bv[k] = __ldcs(xr1 + i);
    }

    // ---- then compute + store ----
    #pragma unroll
    for (int k = 0; k < K3IT; k++) {
        const int i = k * K3T + tid;
        float4 o0, o1;
        o0.x = fmaf(tv[k].x, ca0, cd0) + av[k].x;
        o0.y = fmaf(tv[k].y, ca0, cd0) + av[k].y;
        o0.z = fmaf(tv[k].z, ca0, cd0) + av[k].z;
        o0.w = fmaf(tv[k].w, ca0, cd0) + av[k].w;
        __stcs(zr0 + i, o0);
        o1.x = fmaf(tv[k].x, ca1, cd1) + bv[k].x;
        o1.y = fmaf(tv[k].y, ca1, cd1) + bv[k].y;
        o1.z = fmaf(tv[k].z, ca1, cd1) + bv[k].z;
        o1.w = fmaf(tv[k].w, ca1, cd1) + bv[k].w;
        __stcs(zr1 + i, o1);
    }
}

// ---------------------------------------------------------------------------
extern "C" void kernel_launch(void* const* d_in, const int* in_sizes, int n_in,
                              void* d_out, int out_size)
{
    const float* x     = (const float*)d_in[0];
    const float* g_w   = (const float*)d_in[1];
    const float* g_b   = (const float*)d_in[2];
    const float* th_w  = (const float*)d_in[3];
    const float* th_b  = (const float*)d_in[4];
    const float* ph_w  = (const float*)d_in[5];
    const float* ph_b  = (const float*)d_in[6];
    const float* W_w   = (const float*)d_in[7];
    const float* W_b   = (const float*)d_in[8];
    const float* gamma = (const float*)d_in[9];
    const float* beta  = (const float*)d_in[10];
    const float* mean  = (const float*)d_in[11];
    const float* var   = (const float*)d_in[12];
    float* z = (float*)d_out;

    for (int h = 0; h < SPLITS; h++) {
        const int bbase = h * BH;
        dim3 g1(NTM, CH, BH);                 // 18 x 8 x 16 = 2304 blocks
        k1_dots<<<g1, K1T>>>(x, g_w, g_b, th_w, th_b, ph_w, ph_b, bbase);
        dim3 g3(C_ / K3R, BH);                // 128 x 16 = 2048 blocks
        k3_epilogue<<<g3, K3T>>>(x, z, W_w, W_b, gamma, beta, mean, var, bbase);
    }
}

// round 14
// speedup vs baseline: 1.0305x; 1.0305x over previous
#include <cuda_runtime.h>
#include <cstdint>

// Fixed problem shape
constexpr int B_   = 32;
constexpr int C_   = 256;
constexpr int N_   = 4608;          // 96*48
constexpr int TILE = 64;            // n per block
constexpr int NT   = N_ / TILE;     // 72 tiles per batch
constexpr int TPB  = 256;

// Shared-memory layout (floats)
constexpr int XS_F  = C_ * TILE;    // 16384 : x tile [c][n]
constexpr int OFF_PDG = XS_F;            // 256  : partial g  [q][n]
constexpr int OFF_PDT = OFF_PDG + 256;   // 256  : partial th [q][n]
constexpr int OFF_PDP = OFF_PDT + 256;   // 256  : partial ph [q][n]
constexpr int OFF_SWG = OFF_PDP + 256;   // 256  : g weights
constexpr int OFF_SWT = OFF_SWG + 256;   // 256  : theta weights
constexpr int OFF_SWP = OFF_SWT + 256;   // 256  : phi weights
constexpr int OFF_SA  = OFF_SWP + 256;   // 256  : W_w * inv_std
constexpr int OFF_SD  = OFF_SA  + 256;   // 256  : (W_b-mean)*inv+beta
constexpr int OFF_TH  = OFF_SD  + 256;   // 64   : theta row (16B aligned)
constexpr int OFF_SPS = OFF_TH  + 64;    // 72   : staged tile partials
constexpr int OFF_RED = OFF_SPS + 72;    // 8    : pg warp partials
constexpr int SMEM_F  = OFF_RED + 8;     // 18576 floats
constexpr int SMEM_B  = SMEM_F * 4;      // 74304 bytes

// Scratch (__device__ globals: allocation-free rule; zero-initialized)
__device__ float    g_sp[B_ * NT];
__device__ unsigned g_cnt[B_];
__device__ unsigned g_done[B_];

__device__ __forceinline__ void cp_async16(uint32_t saddr, const void* gptr) {
    asm volatile("cp.async.cg.shared.global [%0], [%1], 16;\n"
                 :: "r"(saddr), "l"(gptr) : "memory");
}

// ---------------------------------------------------------------------------
// Single-pass kernel: one (b, n-tile) per block. x read ONCE from DRAM.
// ---------------------------------------------------------------------------
__global__ __launch_bounds__(TPB)
void k_all(const float* __restrict__ x, float* __restrict__ z,
           const float* __restrict__ gw, const float* __restrict__ gb,
           const float* __restrict__ tw, const float* __restrict__ tb,
           const float* __restrict__ pw, const float* __restrict__ pb,
           const float* __restrict__ Ww, const float* __restrict__ Wb,
           const float* __restrict__ gamma, const float* __restrict__ beta,
           const float* __restrict__ mean,  const float* __restrict__ var)
{
    extern __shared__ float sm[];
    float* xs  = sm;
    float* pdg = sm + OFF_PDG;
    float* pdt = sm + OFF_PDT;
    float* pdp = sm + OFF_PDP;
    float* swg = sm + OFF_SWG;
    float* swt = sm + OFF_SWT;
    float* swp = sm + OFF_SWP;
    float* sA  = sm + OFF_SA;
    float* sD  = sm + OFF_SD;
    float* th  = sm + OFF_TH;
    float* sps = sm + OFF_SPS;
    float* red = sm + OFF_RED;

    const int bid  = blockIdx.x;
    const int b    = bid / NT;
    const int tile = bid - b * NT;
    const int n0   = tile * TILE;
    const int tid  = threadIdx.x;

    // ---- phase 1: issue ALL x-tile loads (cp.async, 16 x 16B per thread) ----
    const float* xg = x + (size_t)b * C_ * N_ + n0;
    {
        uint32_t sbase;
        asm("{ .reg .u64 t; cvta.to.shared.u64 t, %1; cvt.u32.u64 %0, t; }"
            : "=r"(sbase) : "l"(xs));
        #pragma unroll
        for (int k = 0; k < 16; k++) {
            const int chunk = k * TPB + tid;        // 0..4095
            const int c = chunk >> 4;
            const int j = chunk & 15;
            cp_async16(sbase + (uint32_t)(c * TILE + j * 4) * 4u,
                       xg + (size_t)c * N_ + j * 4);
        }
        asm volatile("cp.async.commit_group;\n" ::: "memory");
    }

    // ---- overlap: stage weights + BN coefs (one channel per thread) ----
    {
        swg[tid] = __ldg(gw + tid);
        swt[tid] = __ldg(tw + tid);
        swp[tid] = __ldg(pw + tid);
        const float inv = __ldg(gamma + tid) * rsqrtf(__ldg(var + tid) + 1e-5f);
        sA[tid] = __ldg(Ww + tid) * inv;
        sD[tid] = (__ldg(Wb + tid) - __ldg(mean + tid)) * inv + __ldg(beta + tid);
    }

    asm volatile("cp.async.wait_group 0;\n" ::: "memory");
    __syncthreads();

    // ---- phase 2: dots (thread = (n, c-quarter)) ----
    const int n = tid & (TILE - 1);
    const int q = tid >> 6;                 // 0..3
    {
        float ga = 0.f, ta = 0.f, pa = 0.f;
        const int cb = q * 64;
        #pragma unroll 16
        for (int cc = 0; cc < 64; cc++) {
            const int c = cb + cc;
            const float xv = xs[c * TILE + n];
            ga = fmaf(swg[c], xv, ga);
            ta = fmaf(swt[c], xv, ta);
            pa = fmaf(swp[c], xv, pa);
        }
        pdg[q * TILE + n] = ga;
        pdt[q * TILE + n] = ta;
        pdp[q * TILE + n] = pa;
    }
    __syncthreads();

    // ---- merge quarters, theta row, tile partial of sum(phi*g) ----
    if (tid < TILE) {
        const float G = ((pdg[tid] + pdg[64 + tid]) + (pdg[128 + tid] + pdg[192 + tid])) + __ldg(gb);
        const float P = ((pdp[tid] + pdp[64 + tid]) + (pdp[128 + tid] + pdp[192 + tid])) + __ldg(pb);
        th[tid]       = ((pdt[tid] + pdt[64 + tid]) + (pdt[128 + tid] + pdt[192 + tid])) + __ldg(tb);
        float pg = G * P;
        #pragma unroll
        for (int off = 16; off > 0; off >>= 1)
            pg += __shfl_xor_sync(0xffffffffu, pg, off);
        if ((tid & 31) == 0) red[tid >> 5] = pg;
    }
    __syncthreads();

    if (tid == 0) {
        g_sp[b * NT + tile] = red[0] + red[1];
        __threadfence();
        atomicAdd(&g_cnt[b], 1u);
        // spin until all NT tiles of this batch have published
        while (atomicAdd(&g_cnt[b], 0u) < (unsigned)NT)
            __nanosleep(64);
        __threadfence();
    }
    __syncthreads();

    // stage the 72 partials; every thread then sums in identical fixed order
    if (tid < NT) sps[tid] = g_sp[b * NT + tid];
    __syncthreads();
    float s = 0.f;
    #pragma unroll
    for (int t = 0; t < NT; t++) s += sps[t];
    s *= (1.f / (float)N_);

    // ---- phase 3: epilogue, all from smem: z = th*ca + cd + x ----
    {
        const float4* xs4 = reinterpret_cast<const float4*>(xs);
        const float4* th4 = reinterpret_cast<const float4*>(th);
        #pragma unroll
        for (int k = 0; k < 16; k++) {
            const int f = k * TPB + tid;        // 0..4095
            const int c = f >> 4;
            const int j = f & 15;
            const float ca = sA[c] * s;
            const float cd = sD[c];
            const float4 tv = th4[j];
            const float4 xv = xs4[c * 16 + j];
            float4 o;
            o.x = fmaf(tv.x, ca, cd) + xv.x;
            o.y = fmaf(tv.y, ca, cd) + xv.y;
            o.z = fmaf(tv.z, ca, cd) + xv.z;
            o.w = fmaf(tv.w, ca, cd) + xv.w;
            float4* zp = reinterpret_cast<float4*>(z + ((size_t)b * C_ + c) * N_ + n0) + j;
            __stcs(zp, o);
        }
    }

    // ---- self-reset counters for the next (graph-replayed) launch ----
    __syncthreads();
    if (tid == 0) {
        const unsigned old = atomicAdd(&g_done[b], 1u);
        if (old == (unsigned)(NT - 1)) {
            g_cnt[b]  = 0;
            g_done[b] = 0;
            __threadfence();
        }
    }
}

// ---------------------------------------------------------------------------
extern "C" void kernel_launch(void* const* d_in, const int* in_sizes, int n_in,
                              void* d_out, int out_size)
{
    const float* x     = (const float*)d_in[0];
    const float* g_w   = (const float*)d_in[1];
    const float* g_b   = (const float*)d_in[2];
    const float* th_w  = (const float*)d_in[3];
    const float* th_b  = (const float*)d_in[4];
    const float* ph_w  = (const float*)d_in[5];
    const float* ph_b  = (const float*)d_in[6];
    const float* W_w   = (const float*)d_in[7];
    const float* W_b   = (const float*)d_in[8];
    const float* gamma = (const float*)d_in[9];
    const float* beta  = (const float*)d_in[10];
    const float* mean  = (const float*)d_in[11];
    const float* var   = (const float*)d_in[12];
    float* z = (float*)d_out;

    static bool attr_set = false;
    if (!attr_set) {
        cudaFuncSetAttribute(k_all, cudaFuncAttributeMaxDynamicSharedMemorySize, SMEM_B);
        attr_set = true;
    }

    k_all<<<B_ * NT, TPB, SMEM_B>>>(x, z, g_w, g_b, th_w, th_b, ph_w, ph_b,
                                    W_w, W_b, gamma, beta, mean, var);
}

// round 15
// speedup vs baseline: 1.1093x; 1.0764x over previous
#include <cuda_runtime.h>
#include <cstdint>

// Fixed problem shape
constexpr int B_   = 32;
constexpr int C_   = 256;
constexpr int N_   = 4608;          // 96*48
constexpr int TILE = 64;            // n per block
constexpr int NT   = N_ / TILE;     // 72 tiles per batch
constexpr int TPB  = 512;

// Shared-memory layout (floats)
constexpr int OFF_X   = 0;                 // 16384 : x tile [c][n]
constexpr int OFF_PD  = 16384;             // 1536  : pd g/t/p [8][64] each
//   aliases inside PD region (valid after the merge phase):
constexpr int OFF_SA  = OFF_PD;            // 256 : s*Ww*inv staging (Ww*inv)
constexpr int OFF_SD  = OFF_PD + 256;      // 256 : (Wb-mean)*inv+beta
constexpr int OFF_SPS = OFF_PD + 512;      // 72  : staged tile partials
constexpr int OFF_RED = OFF_PD + 600;      // 8   : pg warp partials
constexpr int OFF_W   = OFF_PD + 1536;     // 768 : g/theta/phi weights
constexpr int OFF_TH  = OFF_W + 768;       // 64  : theta row (16B aligned)
constexpr int SMEM_F  = OFF_TH + 64;       // 18752 floats
constexpr int SMEM_B  = SMEM_F * 4;        // 75008 bytes (3 blocks/SM)

// Scratch (__device__ globals: allocation-free rule; zero-initialized)
__device__ float    g_sp[B_ * NT];
__device__ unsigned g_cnt[B_];
__device__ unsigned g_done[B_];

__device__ __forceinline__ void cp_async16(uint32_t saddr, const void* gptr) {
    asm volatile("cp.async.cg.shared.global [%0], [%1], 16;\n"
                 :: "r"(saddr), "l"(gptr) : "memory");
}

// ---------------------------------------------------------------------------
// Single-pass kernel: one (b, n-tile) per block. x read ONCE from DRAM.
// ---------------------------------------------------------------------------
__global__ __launch_bounds__(TPB)
void k_all(const float* __restrict__ x, float* __restrict__ z,
           const float* __restrict__ gw, const float* __restrict__ gb,
           const float* __restrict__ tw, const float* __restrict__ tb,
           const float* __restrict__ pw, const float* __restrict__ pb,
           const float* __restrict__ Ww, const float* __restrict__ Wb,
           const float* __restrict__ gamma, const float* __restrict__ beta,
           const float* __restrict__ mean,  const float* __restrict__ var)
{
    extern __shared__ float sm[];
    float* xs  = sm + OFF_X;
    float* pdg = sm + OFF_PD;          // [8][64]
    float* pdt = sm + OFF_PD + 512;
    float* pdp = sm + OFF_PD + 1024;
    float* sA  = sm + OFF_SA;          // alias (post-merge)
    float* sD  = sm + OFF_SD;          // alias (post-merge)
    float* sps = sm + OFF_SPS;         // alias (post-merge)
    float* red = sm + OFF_RED;         // alias (post-merge, disjoint)
    float* swg = sm + OFF_W;
    float* swt = sm + OFF_W + 256;
    float* swp = sm + OFF_W + 512;
    float* th  = sm + OFF_TH;

    const int bid  = blockIdx.x;
    const int b    = bid / NT;
    const int tile = bid - b * NT;
    const int n0   = tile * TILE;
    const int tid  = threadIdx.x;

    // ---- phase 1: issue ALL x-tile loads (cp.async, 8 x 16B per thread) ----
    const float* xg = x + (size_t)b * C_ * N_ + n0;
    {
        uint32_t sbase;
        asm("{ .reg .u64 t; cvta.to.shared.u64 t, %1; cvt.u32.u64 %0, t; }"
            : "=r"(sbase) : "l"(xs));
        #pragma unroll
        for (int k = 0; k < 8; k++) {
            const int chunk = k * TPB + tid;        // 0..4095
            const int c = chunk >> 4;
            const int j = chunk & 15;
            cp_async16(sbase + (uint32_t)(c * TILE + j * 4) * 4u,
                       xg + (size_t)c * N_ + j * 4);
        }
        asm volatile("cp.async.commit_group;\n" ::: "memory");
    }

    // ---- overlap: stage projection weights ----
    if (tid < C_) {
        swg[tid] = __ldg(gw + tid);
        swt[tid] = __ldg(tw + tid);
        swp[tid] = __ldg(pw + tid);
    }

    asm volatile("cp.async.wait_group 0;\n" ::: "memory");
    __syncthreads();

    // ---- phase 2: dots (thread = (n, c-eighth)) ----
    const int n = tid & (TILE - 1);
    const int g = tid >> 6;                 // 0..7
    {
        float ga = 0.f, ta = 0.f, pa = 0.f;
        const int cb = g * 32;
        #pragma unroll
        for (int cc = 0; cc < 32; cc++) {
            const int c = cb + cc;
            const float xv = xs[c * TILE + n];
            ga = fmaf(swg[c], xv, ga);
            ta = fmaf(swt[c], xv, ta);
            pa = fmaf(swp[c], xv, pa);
        }
        pdg[g * TILE + n] = ga;
        pdt[g * TILE + n] = ta;
        pdp[g * TILE + n] = pa;
    }
    __syncthreads();

    // ---- merge eighths, theta row, tile partial of sum(phi*g) ----
    if (tid < TILE) {
        float G = __ldg(gb), P = __ldg(pb), T = __ldg(tb);
        #pragma unroll
        for (int q = 0; q < 8; q++) {       // fixed order
            G += pdg[q * TILE + tid];
            P += pdp[q * TILE + tid];
            T += pdt[q * TILE + tid];
        }
        th[tid] = T;
        float pg = G * P;
        #pragma unroll
        for (int off = 16; off > 0; off >>= 1)
            pg += __shfl_xor_sync(0xffffffffu, pg, off);
        if ((tid & 31) == 0) red[tid >> 5] = pg;
    }
    __syncthreads();                        // pd region now dead (except red)

    // ---- publish + spin (thread 0) overlapped with BN-coef staging ----
    if (tid == 0) {
        g_sp[b * NT + tile] = red[0] + red[1];
        __threadfence();
        atomicAdd(&g_cnt[b], 1u);
        while (atomicAdd(&g_cnt[b], 0u) < (unsigned)NT)
            __nanosleep(64);
        __threadfence();
    } else if (tid >= 64 && tid < 64 + C_) {
        const int c = tid - 64;
        const float inv = __ldg(gamma + c) * rsqrtf(__ldg(var + c) + 1e-5f);
        sA[c] = __ldg(Ww + c) * inv;
        sD[c] = (__ldg(Wb + c) - __ldg(mean + c)) * inv + __ldg(beta + c);
    }
    __syncthreads();

    // stage the 72 partials; every thread then sums in identical fixed order
    if (tid < NT) sps[tid] = g_sp[b * NT + tid];
    __syncthreads();
    float s = 0.f;
    #pragma unroll
    for (int t = 0; t < NT; t++) s += sps[t];
    s *= (1.f / (float)N_);

    // ---- phase 3: epilogue, all from smem: z = th*ca + cd + x ----
    {
        const float4* xs4 = reinterpret_cast<const float4*>(xs);
        const float4* th4 = reinterpret_cast<const float4*>(th);
        #pragma unroll
        for (int k = 0; k < 8; k++) {
            const int f = k * TPB + tid;        // 0..4095
            const int c = f >> 4;
            const int j = f & 15;
            const float ca = sA[c] * s;
            const float cd = sD[c];
            const float4 tv = th4[j];
            const float4 xv = xs4[c * 16 + j];
            float4 o;
            o.x = fmaf(tv.x, ca, cd) + xv.x;
            o.y = fmaf(tv.y, ca, cd) + xv.y;
            o.z = fmaf(tv.z, ca, cd) + xv.z;
            o.w = fmaf(tv.w, ca, cd) + xv.w;
            float4* zp = reinterpret_cast<float4*>(z + ((size_t)b * C_ + c) * N_ + n0) + j;
            __stcs(zp, o);
        }
    }

    // ---- self-reset counters for the next (graph-replayed) launch ----
    __syncthreads();
    if (tid == 0) {
        const unsigned old = atomicAdd(&g_done[b], 1u);
        if (old == (unsigned)(NT - 1)) {
            g_cnt[b]  = 0;
            g_done[b] = 0;
            __threadfence();
        }
    }
}

// ---------------------------------------------------------------------------
extern "C" void kernel_launch(void* const* d_in, const int* in_sizes, int n_in,
                              void* d_out, int out_size)
{
    const float* x     = (const float*)d_in[0];
    const float* g_w   = (const float*)d_in[1];
    const float* g_b   = (const float*)d_in[2];
    const float* th_w  = (const float*)d_in[3];
    const float* th_b  = (const float*)d_in[4];
    const float* ph_w  = (const float*)d_in[5];
    const float* ph_b  = (const float*)d_in[6];
    const float* W_w   = (const float*)d_in[7];
    const float* W_b   = (const float*)d_in[8];
    const float* gamma = (const float*)d_in[9];
    const float* beta  = (const float*)d_in[10];
    const float* mean  = (const float*)d_in[11];
    const float* var   = (const float*)d_in[12];
    float* z = (float*)d_out;

    static bool attr_set = false;
    if (!attr_set) {
        cudaFuncSetAttribute(k_all, cudaFuncAttributeMaxDynamicSharedMemorySize, SMEM_B);
        attr_set = true;
    }

    k_all<<<B_ * NT, TPB, SMEM_B>>>(x, z, g_w, g_b, th_w, th_b, ph_w, ph_b,
                                    W_w, W_b, gamma, beta, mean, var);
}